// round 17
// baseline (speedup 1.0000x reference)
#include <cuda_runtime.h>
#include <cuda_fp16.h>
#include <cstdint>
#include <cstddef>

constexpr int Kn = 1024, Cc = 128, Dd = 6272, FFNn = 1024, CPG = 32, DYN = 36864, Mb = 64;

// ---------------- scratch ----------------
__device__ __align__(128) float  g_x   [(size_t)Kn * Dd];
__device__ __align__(128) float  g_flat[(size_t)Kn * Dd];
__device__ __align__(128) float  g_gap [(size_t)Kn * Cc];
__device__ __align__(128) __half g_dynh[(size_t)Kn * DYN];
__device__ __align__(128) __half g_p1[(size_t)3 * Kn * Dd];   // GEMM1 partials / FFN2 partials
__device__ __align__(128) __half g_p2[(size_t)3 * Kn * Dd];   // GEMM2 partials
__device__ __align__(128) __half g_pf[(size_t)4 * Kn * FFNn]; // FFN1 partials

// ---------------- PTX helpers ----------------
__device__ __forceinline__ float f2tf(float x) {
    uint32_t r;
    asm("cvt.rna.tf32.f32 %0, %1;" : "=r"(r) : "f"(x));
    return __uint_as_float(r);
}
__device__ __forceinline__ void mma_tf32(float* c, const uint32_t* a, const uint32_t* b) {
    asm volatile(
        "mma.sync.aligned.m16n8k8.row.col.f32.tf32.tf32.f32 "
        "{%0,%1,%2,%3}, {%4,%5,%6,%7}, {%8,%9}, {%0,%1,%2,%3};"
        : "+f"(c[0]), "+f"(c[1]), "+f"(c[2]), "+f"(c[3])
        : "r"(a[0]), "r"(a[1]), "r"(a[2]), "r"(a[3]), "r"(b[0]), "r"(b[1]));
}
#define CP_A16(dst, src) \
    asm volatile("cp.async.ca.shared.global [%0], [%1], 16;" :: "r"(dst), "l"(src) : "memory")
#define CP_COMMIT() asm volatile("cp.async.commit_group;" ::: "memory")
#define CP_WAIT1()  asm volatile("cp.async.wait_group 1;" ::: "memory")

constexpr int SROW = 20;
constexpr int STAGE_F = 2 * 128 * SROW;     // 5120 floats per stage (A+B)
constexpr int GEMM_SMEM = 3 * STAGE_F * 4;  // 61440 B

// ============================================================
// tf32 GEMM, fp32 A: 128x128 block, 8 warps (32x64), occ 2,
// 3-stage cp.async. Z-way split-K; Z==1 -> C (fp32/fp16 +bias),
// Z>1 -> fp16 partials.
// ============================================================
template<bool OUTHALF>
__global__ void __launch_bounds__(256, 2) gemm_t(
    const float* __restrict__ A, const float* __restrict__ B,
    const float* __restrict__ bias, float* __restrict__ Cf,
    __half* __restrict__ Ch, __half* __restrict__ part,
    int N, int Kd, int KC)
{
    extern __shared__ float sm[];
    const int tid = threadIdx.x;
    const int wid = tid >> 5, lane = tid & 31;
    const int lr = lane >> 2, lc = lane & 3;
    const int m0 = blockIdx.x * 128, n0 = blockIdx.y * 128;
    const int wrow = (wid >> 1) * 32, wcol = (wid & 1) * 64;
    const int Z = gridDim.z;
    const int KCn = (KC + Z - 1) / Z;
    const int kc0 = blockIdx.z * KCn;
    const int KCz = min(KCn, KC - kc0);
    const int M = gridDim.x * 128;

    const uint32_t smem_base = (uint32_t)__cvta_generic_to_shared(sm);
    const int c0r = tid >> 2, c0q = tid & 3;
    const int c1r = (tid + 256) >> 2;

    const float* Abase = A + (size_t)m0 * Kd;
    const float* Bbase = B + (size_t)n0 * Kd;

    auto load_stage = [&](int s, int kt) {
        const uint32_t base = smem_base + (uint32_t)s * (STAGE_F * 4);
        const int ko = (kc0 + kt) * 16;
        CP_A16(base + (uint32_t)(c0r * SROW + c0q * 4) * 4,              Abase + (size_t)c0r * Kd + ko + c0q * 4);
        CP_A16(base + (uint32_t)(c1r * SROW + c0q * 4) * 4,              Abase + (size_t)c1r * Kd + ko + c0q * 4);
        CP_A16(base + (uint32_t)(128 * SROW + c0r * SROW + c0q * 4) * 4, Bbase + (size_t)c0r * Kd + ko + c0q * 4);
        CP_A16(base + (uint32_t)(128 * SROW + c1r * SROW + c0q * 4) * 4, Bbase + (size_t)c1r * Kd + ko + c0q * 4);
    };

    float acc[2][8][4];
    #pragma unroll
    for (int mt = 0; mt < 2; mt++)
        #pragma unroll
        for (int nt = 0; nt < 8; nt++)
            #pragma unroll
            for (int q = 0; q < 4; q++) acc[mt][nt][q] = 0.f;

    load_stage(0, 0); CP_COMMIT();
    if (KCz > 1) load_stage(1, 1);
    CP_COMMIT();

    for (int kt = 0; kt < KCz; ++kt) {
        CP_WAIT1();
        __syncthreads();
        const int nx = kt + 2;
        if (nx < KCz) load_stage(nx % 3, nx);
        CP_COMMIT();

        const float* As = sm + (kt % 3) * STAGE_F;
        const float* Bs = As + 128 * SROW;
        #pragma unroll
        for (int kk = 0; kk < 2; kk++) {
            const int kb = kk * 8;
            uint32_t a[2][4], b[8][2];
            #pragma unroll
            for (int mt = 0; mt < 2; mt++) {
                const int r = wrow + mt * 16 + lr;
                a[mt][0] = __float_as_uint(f2tf(As[r * SROW + kb + lc]));
                a[mt][1] = __float_as_uint(f2tf(As[(r + 8) * SROW + kb + lc]));
                a[mt][2] = __float_as_uint(f2tf(As[r * SROW + kb + lc + 4]));
                a[mt][3] = __float_as_uint(f2tf(As[(r + 8) * SROW + kb + lc + 4]));
            }
            #pragma unroll
            for (int nt = 0; nt < 8; nt++) {
                const int n = wcol + nt * 8 + lr;
                b[nt][0] = __float_as_uint(f2tf(Bs[n * SROW + kb + lc]));
                b[nt][1] = __float_as_uint(f2tf(Bs[n * SROW + kb + lc + 4]));
            }
            #pragma unroll
            for (int mt = 0; mt < 2; mt++)
                #pragma unroll
                for (int nt = 0; nt < 8; nt++)
                    mma_tf32(acc[mt][nt], a[mt], b[nt]);
        }
    }

    if (Z == 1) {
        #pragma unroll
        for (int mt = 0; mt < 2; mt++) {
            #pragma unroll
            for (int nt = 0; nt < 8; nt++) {
                const int row0 = m0 + wrow + mt * 16 + lr;
                const int col  = n0 + wcol + nt * 8 + 2 * lc;
                const float b0 = bias[col], b1 = bias[col + 1];
                float v0 = acc[mt][nt][0] + b0, v1 = acc[mt][nt][1] + b1;
                float v2 = acc[mt][nt][2] + b0, v3 = acc[mt][nt][3] + b1;
                if (OUTHALF) {
                    *(__half2*)(Ch + (size_t)row0 * N + col)       = __floats2half2_rn(v0, v1);
                    *(__half2*)(Ch + (size_t)(row0 + 8) * N + col) = __floats2half2_rn(v2, v3);
                } else {
                    *(float2*)(Cf + (size_t)row0 * N + col)       = make_float2(v0, v1);
                    *(float2*)(Cf + (size_t)(row0 + 8) * N + col) = make_float2(v2, v3);
                }
            }
        }
    } else {
        __half* P = part + (size_t)blockIdx.z * M * N;
        #pragma unroll
        for (int mt = 0; mt < 2; mt++) {
            #pragma unroll
            for (int nt = 0; nt < 8; nt++) {
                const int row0 = m0 + wrow + mt * 16 + lr;
                const int col  = n0 + wcol + nt * 8 + 2 * lc;
                *(__half2*)(P + (size_t)row0 * N + col)       = __floats2half2_rn(acc[mt][nt][0], acc[mt][nt][1]);
                *(__half2*)(P + (size_t)(row0 + 8) * N + col) = __floats2half2_rn(acc[mt][nt][2], acc[mt][nt][3]);
            }
        }
    }
}

// ============================================================
// tf32 GEMM, A assembled from ZP fp16 partial planes:
//   A[m][k] = f( sum_z Apart[z][m][k] + biasA[k] ),  f = relu opt.
// A side: explicit LDG->regs (iter kt-2) -> STS (iter kt-1).
// B side: cp.async 3-stage (as gemm_t). Z-way split-K output.
// ============================================================
template<int ZP, bool RELUA>
__global__ void __launch_bounds__(256, 2) gemm_tp(
    const __half* __restrict__ Apart, const float* __restrict__ biasA,
    const float* __restrict__ B, __half* __restrict__ part,
    int N, int Kd, int KC)
{
    extern __shared__ float sm[];
    const int tid = threadIdx.x;
    const int wid = tid >> 5, lane = tid & 31;
    const int lr = lane >> 2, lc = lane & 3;
    const int m0 = blockIdx.x * 128, n0 = blockIdx.y * 128;
    const int wrow = (wid >> 1) * 32, wcol = (wid & 1) * 64;
    const int Z = gridDim.z;
    const int KCn = (KC + Z - 1) / Z;
    const int kc0 = blockIdx.z * KCn;
    const int KCz = min(KCn, KC - kc0);
    const int M = gridDim.x * 128;
    const size_t planeA = (size_t)M * Kd;

    const uint32_t smem_base = (uint32_t)__cvta_generic_to_shared(sm);
    const int c0r = tid >> 2, c0q = tid & 3;
    const int c1r = (tid + 256) >> 2;

    const __half* Abase = Apart + (size_t)m0 * Kd;
    const float* Bbase = B + (size_t)n0 * Kd;

    float4 ra[2];                         // assembled A chunk (2 rows x 4 floats)
    auto ldgA = [&](int c) {
        const int ko = (kc0 + c) * 16 + c0q * 4;
        const float4 bb = *(const float4*)(biasA + ko);
        #pragma unroll
        for (int i = 0; i < 2; i++) {
            const size_t off = (size_t)(i == 0 ? c0r : c1r) * Kd + ko;
            float4 v = bb;
            #pragma unroll
            for (int z = 0; z < ZP; z++) {
                uint2 u = *(const uint2*)(Abase + z * planeA + off);
                float2 lo = __half22float2(*(const __half2*)&u.x);
                float2 hi = __half22float2(*(const __half2*)&u.y);
                v.x += lo.x; v.y += lo.y; v.z += hi.x; v.w += hi.y;
            }
            if (RELUA) {
                v.x = fmaxf(v.x, 0.f); v.y = fmaxf(v.y, 0.f);
                v.z = fmaxf(v.z, 0.f); v.w = fmaxf(v.w, 0.f);
            }
            ra[i] = v;
        }
    };
    auto stsA = [&](int s) {
        float* d = sm + s * STAGE_F;
        *(float4*)(d + c0r * SROW + c0q * 4) = ra[0];
        *(float4*)(d + c1r * SROW + c0q * 4) = ra[1];
    };
    auto cpB = [&](int s, int kt) {
        const uint32_t base = smem_base + (uint32_t)s * (STAGE_F * 4) + 128 * SROW * 4;
        const int ko = (kc0 + kt) * 16;
        CP_A16(base + (uint32_t)(c0r * SROW + c0q * 4) * 4, Bbase + (size_t)c0r * Kd + ko + c0q * 4);
        CP_A16(base + (uint32_t)(c1r * SROW + c0q * 4) * 4, Bbase + (size_t)c1r * Kd + ko + c0q * 4);
    };

    float acc[2][8][4];
    #pragma unroll
    for (int mt = 0; mt < 2; mt++)
        #pragma unroll
        for (int nt = 0; nt < 8; nt++)
            #pragma unroll
            for (int q = 0; q < 4; q++) acc[mt][nt][q] = 0.f;

    // prologue: A chunk0 -> stage0; A chunk1 -> regs; B chunks 0,1 via cp.async
    ldgA(0); stsA(0);
    if (KCz > 1) ldgA(1);
    cpB(0, 0); CP_COMMIT();
    if (KCz > 1) cpB(1, 1);
    CP_COMMIT();

    for (int kt = 0; kt < KCz; ++kt) {
        CP_WAIT1();
        __syncthreads();
        if (kt + 1 < KCz) stsA((kt + 1) % 3);           // regs hold chunk kt+1
        if (kt + 2 < KCz) { ldgA(kt + 2); cpB((kt + 2) % 3, kt + 2); }
        CP_COMMIT();

        const float* As = sm + (kt % 3) * STAGE_F;
        const float* Bs = As + 128 * SROW;
        #pragma unroll
        for (int kk = 0; kk < 2; kk++) {
            const int kb = kk * 8;
            uint32_t a[2][4], b[8][2];
            #pragma unroll
            for (int mt = 0; mt < 2; mt++) {
                const int r = wrow + mt * 16 + lr;
                a[mt][0] = __float_as_uint(f2tf(As[r * SROW + kb + lc]));
                a[mt][1] = __float_as_uint(f2tf(As[(r + 8) * SROW + kb + lc]));
                a[mt][2] = __float_as_uint(f2tf(As[r * SROW + kb + lc + 4]));
                a[mt][3] = __float_as_uint(f2tf(As[(r + 8) * SROW + kb + lc + 4]));
            }
            #pragma unroll
            for (int nt = 0; nt < 8; nt++) {
                const int n = wcol + nt * 8 + lr;
                b[nt][0] = __float_as_uint(f2tf(Bs[n * SROW + kb + lc]));
                b[nt][1] = __float_as_uint(f2tf(Bs[n * SROW + kb + lc + 4]));
            }
            #pragma unroll
            for (int mt = 0; mt < 2; mt++)
                #pragma unroll
                for (int nt = 0; nt < 8; nt++)
                    mma_tf32(acc[mt][nt], a[mt], b[nt]);
        }
        __syncthreads();   // protect stage being STS'd next iter from early writers
    }

    __half* P = part + (size_t)blockIdx.z * M * N;
    #pragma unroll
    for (int mt = 0; mt < 2; mt++) {
        #pragma unroll
        for (int nt = 0; nt < 8; nt++) {
            const int row0 = m0 + wrow + mt * 16 + lr;
            const int col  = n0 + wcol + nt * 8 + 2 * lc;
            *(__half2*)(P + (size_t)row0 * N + col)       = __floats2half2_rn(acc[mt][nt][0], acc[mt][nt][1]);
            *(__half2*)(P + (size_t)(row0 + 8) * N + col) = __floats2half2_rn(acc[mt][nt][2], acc[mt][nt][3]);
        }
    }
}

// ============================================================
// merge(fp16 partials) + residual + LN (+ optional GAP), 512 threads
// ============================================================
__global__ void __launch_bounds__(512) merge_ln(
    const __half* __restrict__ part, const float* __restrict__ bias,
    const float* __restrict__ res, const float* __restrict__ gamma,
    const float* __restrict__ beta, float* __restrict__ out,
    float* __restrict__ gapOut, int N, int Z, size_t MN)
{
    const int row = blockIdx.x, t = threadIdx.x;
    const size_t base = (size_t)row * N;
    __shared__ float rs[16], rs2[16], smean, sinv;

    float4 val[4];
    float s = 0.f, s2 = 0.f;
    #pragma unroll
    for (int j = 0; j < 4; j++) {
        const int i = (t + j * 512) * 4;
        if (i < N) {
            const __half2* p0 = (const __half2*)(part + base + i);
            float2 a = __half22float2(p0[0]), b = __half22float2(p0[1]);
            float4 v = make_float4(a.x, a.y, b.x, b.y);
            for (int z = 1; z < Z; z++) {
                const __half2* pz = (const __half2*)(part + (size_t)z * MN + base + i);
                float2 c = __half22float2(pz[0]), d = __half22float2(pz[1]);
                v.x += c.x; v.y += c.y; v.z += d.x; v.w += d.y;
            }
            float4 bb = *(const float4*)(bias + i);
            float4 rr = *(const float4*)(res + base + i);
            v.x += bb.x + rr.x; v.y += bb.y + rr.y;
            v.z += bb.z + rr.z; v.w += bb.w + rr.w;
            val[j] = v;
            s  += v.x + v.y + v.z + v.w;
            s2 += v.x * v.x + v.y * v.y + v.z * v.z + v.w * v.w;
        }
    }
    #pragma unroll
    for (int o = 16; o > 0; o >>= 1) {
        s  += __shfl_xor_sync(~0u, s, o);
        s2 += __shfl_xor_sync(~0u, s2, o);
    }
    if ((t & 31) == 0) { rs[t >> 5] = s; rs2[t >> 5] = s2; }
    __syncthreads();
    if (t == 0) {
        float ts = 0.f, ts2 = 0.f;
        #pragma unroll
        for (int i = 0; i < 16; i++) { ts += rs[i]; ts2 += rs2[i]; }
        float mean = ts / N;
        smean = mean;
        sinv = rsqrtf(ts2 / N - mean * mean + 1e-5f);
    }
    __syncthreads();
    const float mean = smean, inv = sinv;

    #pragma unroll
    for (int j = 0; j < 4; j++) {
        const int i = (t + j * 512) * 4;
        if (i < N) {
            float4 gg = *(const float4*)(gamma + i);
            float4 be = *(const float4*)(beta + i);
            float4 v = val[j];
            v.x = (v.x - mean) * inv * gg.x + be.x;
            v.y = (v.y - mean) * inv * gg.y + be.y;
            v.z = (v.z - mean) * inv * gg.z + be.z;
            v.w = (v.w - mean) * inv * gg.w + be.w;
            *(float4*)(out + base + i) = v;
        }
    }
    if (gapOut) {
        __syncthreads();
        if (t < Cc) {
            const float* p = out + base + t * 49;
            float a = 0.f;
            #pragma unroll
            for (int q = 0; q < 49; q++) a += p[q];
            gapOut[(size_t)row * Cc + t] = a * (1.f / 49.f);
        }
    }
}

// ============================================================
// dynconv (fp16 dyn weights, vectorized loads) + residual + fused LN2
// ============================================================
__global__ void __launch_bounds__(128) dynconv_ln(
    const float* __restrict__ x, const __half* __restrict__ dyn,
    const float* __restrict__ g2, const float* __restrict__ b2,
    float* __restrict__ out)
{
    const int s = blockIdx.x, t = threadIdx.x;
    __shared__ float sIn[Cc][81];
    __shared__ float rs[4], rs2[4], smean, sinv;
    float* sc = sIn[t];
    #pragma unroll
    for (int i = 0; i < 81; i++) sc[i] = 0.f;
    const float* xp = x + ((size_t)s * Cc + t) * 49;
    #pragma unroll
    for (int y = 0; y < 7; y++)
        #pragma unroll
        for (int xx = 0; xx < 7; xx++)
            sc[(y + 1) * 9 + xx + 1] = xp[y * 7 + xx];
    __syncthreads();

    const int grp = t >> 5;
    const uint4* wb4 = (const uint4*)(dyn + (size_t)s * DYN + (size_t)t * (CPG * 9));
    const float* ib = &sIn[grp * CPG][0];
    float acc[49];
    #pragma unroll
    for (int i = 0; i < 49; i++) acc[i] = 0.f;

    for (int c = 0; c < 4; c++) {
        uint4 w4[9];
        #pragma unroll
        for (int j = 0; j < 9; j++) w4[j] = wb4[c * 9 + j];
        const __half* wh = (const __half*)w4;
        #pragma unroll
        for (int i2 = 0; i2 < 8; i2++) {
            const float* in = ib + (c * 8 + i2) * 81;
            const float w0 = __half2float(wh[i2 * 9 + 0]);
            const float w1 = __half2float(wh[i2 * 9 + 1]);
            const float w2 = __half2float(wh[i2 * 9 + 2]);
            const float w3 = __half2float(wh[i2 * 9 + 3]);
            const float w4v = __half2float(wh[i2 * 9 + 4]);
            const float w5 = __half2float(wh[i2 * 9 + 5]);
            const float w6 = __half2float(wh[i2 * 9 + 6]);
            const float w7 = __half2float(wh[i2 * 9 + 7]);
            const float w8 = __half2float(wh[i2 * 9 + 8]);
            #pragma unroll
            for (int y = 0; y < 7; y++) {
                #pragma unroll
                for (int xx = 0; xx < 7; xx++) {
                    float a = acc[y * 7 + xx];
                    a += w0 * in[y * 9 + xx]       + w1 * in[y * 9 + xx + 1]       + w2 * in[y * 9 + xx + 2];
                    a += w3 * in[(y + 1) * 9 + xx] + w4v * in[(y + 1) * 9 + xx + 1] + w5 * in[(y + 1) * 9 + xx + 2];
                    a += w6 * in[(y + 2) * 9 + xx] + w7 * in[(y + 2) * 9 + xx + 1] + w8 * in[(y + 2) * 9 + xx + 2];
                    acc[y * 7 + xx] = a;
                }
            }
        }
    }

    const float* ms = sIn[t];
    float ss = 0.f, ss2 = 0.f;
    #pragma unroll
    for (int j = 0; j < 49; j++) {
        float yv = acc[j] + ms[(j / 7 + 1) * 9 + (j % 7) + 1];
        acc[j] = yv;
        ss += yv; ss2 += yv * yv;
    }
    #pragma unroll
    for (int o = 16; o > 0; o >>= 1) {
        ss  += __shfl_xor_sync(~0u, ss, o);
        ss2 += __shfl_xor_sync(~0u, ss2, o);
    }
    if ((t & 31) == 0) { rs[t >> 5] = ss; rs2[t >> 5] = ss2; }
    __syncthreads();
    if (t == 0) {
        float ts = rs[0] + rs[1] + rs[2] + rs[3];
        float ts2 = rs2[0] + rs2[1] + rs2[2] + rs2[3];
        float mean = ts / Dd;
        smean = mean;
        sinv = rsqrtf(ts2 / Dd - mean * mean + 1e-5f);
    }
    __syncthreads();
    const float mean = smean, inv = sinv;
    float* op = out + ((size_t)s * Cc + t) * 49;
    const float* gp = g2 + t * 49;
    const float* bp = b2 + t * 49;
    #pragma unroll
    for (int j = 0; j < 49; j++)
        op[j] = (acc[j] - mean) * inv * gp[j] + bp[j];
}

// ============================================================
// cost matrix
// ============================================================
__global__ void __launch_bounds__(256) cost_kernel(
    const float* __restrict__ rb, const float* __restrict__ cb, float* __restrict__ out)
{
    __shared__ float sR[Mb * 4], sC[Mb * 4], sdist[Mb * Mb], rm[8], sMax;
    const int t = threadIdx.x;
    sR[t] = rb[t]; sC[t] = cb[t];
    __syncthreads();
    float lm = 0.f;
    for (int idx = t; idx < Mb * Mb; idx += 256) {
        int i = idx >> 6, j = idx & 63;
        float d = fabsf((sR[i * 4] + sR[i * 4 + 2]) * 0.5f - (sC[j * 4] + sC[j * 4 + 2]) * 0.5f)
                + fabsf((sR[i * 4 + 1] + sR[i * 4 + 3]) * 0.5f - (sC[j * 4 + 1] + sC[j * 4 + 3]) * 0.5f);
        sdist[idx] = d;
        lm = fmaxf(lm, d);
    }
    #pragma unroll
    for (int o = 16; o > 0; o >>= 1) lm = fmaxf(lm, __shfl_xor_sync(~0u, lm, o));
    if ((t & 31) == 0) rm[t >> 5] = lm;
    __syncthreads();
    if (t == 0) {
        float m = 0.f;
        #pragma unroll
        for (int i = 0; i < 8; i++) m = fmaxf(m, rm[i]);
        sMax = fmaxf(m, 1.f);
    }
    __syncthreads();
    const float dmax = sMax;
    for (int idx = t; idx < Mb * Mb; idx += 256) {
        int i = idx >> 6, j = idx & 63;
        float ax0 = sR[i*4], ay0 = sR[i*4+1], ax1 = sR[i*4+2], ay1 = sR[i*4+3];
        float bx0 = sC[j*4], by0 = sC[j*4+1], bx1 = sC[j*4+2], by1 = sC[j*4+3];
        float areaA = (ax1 - ax0) * (ay1 - ay0), areaB = (bx1 - bx0) * (by1 - by0);
        float w = fmaxf(fminf(ax1, bx1) - fmaxf(ax0, bx0), 0.f);
        float h = fmaxf(fminf(ay1, by1) - fmaxf(ay0, by0), 0.f);
        float inter = w * h;
        out[idx] = -inter / (areaA + areaB - inter) + 0.5f * sdist[idx] / dmax;
    }
}

// ============================================================
// host launcher
// ============================================================
extern "C" void kernel_launch(void* const* d_in, const int* in_sizes, int n_in,
                              void* d_out, int out_size)
{
    const float* wf     = (const float*)d_in[0];
    const float* rf     = (const float*)d_in[1];
    const float* refb   = (const float*)d_in[2];
    const float* curb   = (const float*)d_in[3];
    // d_in[4..7] dead (softmax over one key == 1 -> attn == v)
    const float* wv     = (const float*)d_in[8];
    const float* bv     = (const float*)d_in[9];
    const float* wo     = (const float*)d_in[10];
    const float* bo     = (const float*)d_in[11];
    const float* g1     = (const float*)d_in[12];
    const float* b1     = (const float*)d_in[13];
    const float* wgen_w = (const float*)d_in[14];
    const float* wgen_b = (const float*)d_in[15];
    const float* g2     = (const float*)d_in[16];
    const float* b2     = (const float*)d_in[17];
    const float* wf1    = (const float*)d_in[18];
    const float* bf1    = (const float*)d_in[19];
    const float* wf2    = (const float*)d_in[20];
    const float* bf2    = (const float*)d_in[21];
    const float* g3     = (const float*)d_in[22];
    const float* b3     = (const float*)d_in[23];
    float* out = (float*)d_out;

    float *x, *flat, *gap;
    __half *dynh, *p1, *p2, *pf;
    cudaGetSymbolAddress((void**)&x, g_x);       cudaGetSymbolAddress((void**)&flat, g_flat);
    cudaGetSymbolAddress((void**)&gap, g_gap);   cudaGetSymbolAddress((void**)&dynh, g_dynh);
    cudaGetSymbolAddress((void**)&p1, g_p1);     cudaGetSymbolAddress((void**)&p2, g_p2);
    cudaGetSymbolAddress((void**)&pf, g_pf);

    cudaFuncSetAttribute(gemm_t<false>,      cudaFuncAttributeMaxDynamicSharedMemorySize, GEMM_SMEM);
    cudaFuncSetAttribute(gemm_t<true>,       cudaFuncAttributeMaxDynamicSharedMemorySize, GEMM_SMEM);
    cudaFuncSetAttribute(gemm_tp<3, false>,  cudaFuncAttributeMaxDynamicSharedMemorySize, GEMM_SMEM);
    cudaFuncSetAttribute(gemm_tp<4, true>,   cudaFuncAttributeMaxDynamicSharedMemorySize, GEMM_SMEM);

    const size_t MN1 = (size_t)Kn * Dd;

    // 1. GEMM1: raw v partials = rf @ wv^T              (Z=3 -> p1)
    gemm_t<false><<<dim3(8, 49, 3), 256, GEMM_SMEM>>>(rf, wv, bv, nullptr, nullptr, p1, Dd, Dd, 392);
    // 2. GEMM2: A = sum(p1)+bv  (== v), B = wo          (Z=3 -> p2)
    gemm_tp<3, false><<<dim3(8, 49, 3), 256, GEMM_SMEM>>>(p1, bv, wo, p2, Dd, Dd, 392);
    // 3. x = LN1(sum(p2) + bo + wf), gap
    merge_ln<<<Kn, 512>>>(p2, bo, wf, g1, b1, x, gap, Dd, 3, MN1);
    // 4. dyn(half) = gap @ wgen^T + wgen_b              (Z=1, fp16 out)
    gemm_t<true><<<dim3(8, 288, 1), 256, GEMM_SMEM>>>(gap, wgen_w, wgen_b, nullptr, dynh, nullptr, DYN, Cc, 8);
    // 5. flat = LN2(dynconv(x) + x)
    dynconv_ln<<<Kn, 128>>>(x, dynh, g2, b2, flat);
    // 6. FFN1: raw h partials = flat @ wf1^T            (Z=4 -> pf)
    gemm_t<false><<<dim3(8, 8, 4), 256, GEMM_SMEM>>>(flat, wf1, bf1, nullptr, nullptr, pf, FFNn, Dd, 392);
    // 7. FFN2: A = relu(sum(pf)+bf1) (== h), B = wf2    (Z=3 -> p1 reuse)
    gemm_tp<4, true><<<dim3(8, 49, 3), 256, GEMM_SMEM>>>(pf, bf1, wf2, p1, Dd, FFNn, 64);
    // 8. out = LN3(sum(p1) + bf2 + flat)
    merge_ln<<<Kn, 512>>>(p1, bf2, flat, g3, b3, out, nullptr, Dd, 3, MN1);
    // 9. cost matrix
    cost_kernel<<<1, 256>>>(refb, curb, out + (size_t)Kn * Dd);
}